// round 4
// baseline (speedup 1.0000x reference)
#include <cuda_runtime.h>
#include <math.h>
#include <stdint.h>

// Problem constants
#define B_     8
#define CIN_   64
#define COUT_  128
#define KH_    3
#define KW_    3
#define K_     9
#define H_     64
#define W_     64
#define P_     4096        // H*W = HO*WO
#define CK_    576         // CIN*K

#define BM 128
#define BN 64
#define BKK 16
#define NSTEP (CK_ / BKK)   // 36
#define LDA 136             // As row pad
#define LDB 72              // Bs row pad
#define NTHR 512

__device__ __forceinline__ uint32_t f2tf32(float f) {
    uint32_t u;
    asm("cvt.rna.tf32.f32 %0, %1;" : "=r"(u) : "f"(f));
    return u;
}

// ---------------------------------------------------------------------------
// Fused deformable-im2col + TF32 tensor-core GEMM.
// Block = (batch b, 64-pixel n-tile). Produces its own B tiles by bilinear
// gather from rgb (L2-resident); no col scratch, no second kernel.
// ---------------------------------------------------------------------------
__global__ __launch_bounds__(NTHR)
void fused_kernel(const float* __restrict__ rgb,
                  const float* __restrict__ offsets,
                  const float* __restrict__ weight,
                  const float* __restrict__ bias,
                  float* __restrict__ out) {
    __shared__ float4 metaW[K_ * BN];          // bilinear weights per (k,p)
    __shared__ int4   metaI[K_ * BN];          // 4 gather indices per (k,p)
    __shared__ uint32_t As[2][BKK][LDA];       // tf32 A tiles [k][m_perm]
    __shared__ uint32_t Bs[2][BKK][LDB];       // tf32 B tiles [k][n]

    const int b   = blockIdx.z;
    const int n0  = blockIdx.x * BN;
    const int tid = threadIdx.x;
    const int lane = tid & 31;
    const int wid  = tid >> 5;
    const int m_off = (wid & 3) * 32;
    const int n_off = (wid >> 2) * 16;
    const int qq = lane >> 2;     // 0..7
    const int rr = lane & 3;      // 0..3

    // ---- Phase 0: sampling metadata for 9 k-positions x 64 pixels ----
    {
        const float* offb = offsets + (size_t)b * 2 * K_ * P_;
        for (int e = tid; e < K_ * BN; e += NTHR) {
            int k = e >> 6;           // 0..8
            int j = e & 63;
            int p = n0 + j;
            int oy = p >> 6;
            int ox = p & 63;

            float dy = offb[(2 * k    ) * P_ + p];
            float dx = offb[(2 * k + 1) * P_ + p];

            float y = (float)(oy - 1 + k / KW_) + dy;
            float x = (float)(ox - 1 + k % KW_) + dx;

            float y0f = floorf(y);
            float x0f = floorf(x);
            float fy = y - y0f;
            float fx = x - x0f;
            int y0 = (int)y0f, x0 = (int)x0f;
            int y1 = y0 + 1,   x1 = x0 + 1;

            float w00 = (1.f - fy) * (1.f - fx);
            float w01 = (1.f - fy) * fx;
            float w10 = fy * (1.f - fx);
            float w11 = fy * fx;

            bool vy0 = (y0 >= 0) & (y0 < H_);
            bool vy1 = (y1 >= 0) & (y1 < H_);
            bool vx0 = (x0 >= 0) & (x0 < W_);
            bool vx1 = (x1 >= 0) & (x1 < W_);
            if (!(vy0 & vx0)) w00 = 0.f;
            if (!(vy0 & vx1)) w01 = 0.f;
            if (!(vy1 & vx0)) w10 = 0.f;
            if (!(vy1 & vx1)) w11 = 0.f;

            int cy0 = min(max(y0, 0), H_ - 1);
            int cy1 = min(max(y1, 0), H_ - 1);
            int cx0 = min(max(x0, 0), W_ - 1);
            int cx1 = min(max(x1, 0), W_ - 1);

            metaW[e] = make_float4(w00, w01, w10, w11);
            metaI[e] = make_int4(cy0 * W_ + cx0, cy0 * W_ + cx1,
                                 cy1 * W_ + cx0, cy1 * W_ + cx1);
        }
    }
    __syncthreads();

    // ---- producer mappings ----
    const int kk_p = tid >> 5;           // 0..15 (B k-row)
    const int n_p  = (lane) * 2;         // 0..62 (B n-pair)
    const int a_row = tid >> 2;          // 0..127 (A m-row)
    const int a_k   = (tid & 3) * 4;     // 0,4,8,12 (A k-offset)
    // pair rows (m, m+8) adjacently within each 16-row group
    const int a_row_p = (a_row & ~15) | (((a_row & 7) << 1) | ((a_row >> 3) & 1));

    const float* imgb = rgb + (size_t)b * CIN_ * P_;

    float acc[2][2][4];
    #pragma unroll
    for (int i = 0; i < 2; i++)
        #pragma unroll
        for (int j = 0; j < 2; j++)
            #pragma unroll
            for (int c = 0; c < 4; c++) acc[i][j][c] = 0.f;

    // ---- prologue: produce tile 0 into buffer 0 ----
    {
        int ck = kk_p;
        int c  = ck / K_;
        int kq = ck - c * K_;
        const float* img_c = imgb + (size_t)c * P_;
        int mb = kq * 64 + n_p;
        float4 w0 = metaW[mb];     int4 i0 = metaI[mb];
        float4 w1 = metaW[mb + 1]; int4 i1 = metaI[mb + 1];
        float v0 = w0.x * img_c[i0.x] + w0.y * img_c[i0.y]
                 + w0.z * img_c[i0.z] + w0.w * img_c[i0.w];
        float v1 = w1.x * img_c[i1.x] + w1.y * img_c[i1.y]
                 + w1.z * img_c[i1.z] + w1.w * img_c[i1.w];
        Bs[0][kk_p][n_p]     = f2tf32(v0);
        Bs[0][kk_p][n_p + 1] = f2tf32(v1);

        float4 pa = *(const float4*)&weight[(size_t)a_row * CK_ + a_k];
        As[0][a_k + 0][a_row_p] = f2tf32(pa.x);
        As[0][a_k + 1][a_row_p] = f2tf32(pa.y);
        As[0][a_k + 2][a_row_p] = f2tf32(pa.z);
        As[0][a_k + 3][a_row_p] = f2tf32(pa.w);
    }

    int cur = 0;
    for (int t = 0; t < NSTEP; t++) {
        __syncthreads();   // buf[cur] ready; buf[cur^1] reads from t-1 done

        // issue next tile's gathers + A load (latency hidden under mma)
        float4 w0, w1, pa;
        float g0x, g0y, g0z, g0w, g1x, g1y, g1z, g1w;
        if (t + 1 < NSTEP) {
            int ck = (t + 1) * BKK + kk_p;
            int c  = ck / K_;
            int kq = ck - c * K_;
            const float* img_c = imgb + (size_t)c * P_;
            int mb = kq * 64 + n_p;
            w0 = metaW[mb];     int4 i0 = metaI[mb];
            w1 = metaW[mb + 1]; int4 i1 = metaI[mb + 1];
            g0x = img_c[i0.x]; g0y = img_c[i0.y];
            g0z = img_c[i0.z]; g0w = img_c[i0.w];
            g1x = img_c[i1.x]; g1y = img_c[i1.y];
            g1z = img_c[i1.z]; g1w = img_c[i1.w];
            pa = *(const float4*)&weight[(size_t)a_row * CK_ + (t + 1) * BKK + a_k];
        }

        // mma on current buffer
        #pragma unroll
        for (int ks = 0; ks < 2; ks++) {
            const int kk = ks * 8;
            uint32_t bf[2][2];
            #pragma unroll
            for (int bn = 0; bn < 2; bn++) {
                bf[bn][0] = Bs[cur][kk + rr    ][n_off + 8 * bn + qq];
                bf[bn][1] = Bs[cur][kk + rr + 4][n_off + 8 * bn + qq];
            }
            uint32_t af[2][4];
            #pragma unroll
            for (int am = 0; am < 2; am++) {
                uint2 v0 = *(const uint2*)&As[cur][kk + rr    ][m_off + 16 * am + 2 * qq];
                uint2 v1 = *(const uint2*)&As[cur][kk + rr + 4][m_off + 16 * am + 2 * qq];
                af[am][0] = v0.x; af[am][1] = v0.y;
                af[am][2] = v1.x; af[am][3] = v1.y;
            }
            #pragma unroll
            for (int am = 0; am < 2; am++)
                #pragma unroll
                for (int bn = 0; bn < 2; bn++) {
                    asm volatile(
                        "mma.sync.aligned.m16n8k8.row.col.f32.tf32.tf32.f32 "
                        "{%0,%1,%2,%3}, {%4,%5,%6,%7}, {%8,%9}, {%0,%1,%2,%3};"
                        : "+f"(acc[am][bn][0]), "+f"(acc[am][bn][1]),
                          "+f"(acc[am][bn][2]), "+f"(acc[am][bn][3])
                        : "r"(af[am][0]), "r"(af[am][1]),
                          "r"(af[am][2]), "r"(af[am][3]),
                          "r"(bf[bn][0]), "r"(bf[bn][1]));
                }
        }

        // combine gathered values and store next tile
        if (t + 1 < NSTEP) {
            int nxt = cur ^ 1;
            float v0 = w0.x * g0x + w0.y * g0y + w0.z * g0z + w0.w * g0w;
            float v1 = w1.x * g1x + w1.y * g1y + w1.z * g1z + w1.w * g1w;
            Bs[nxt][kk_p][n_p]     = f2tf32(v0);
            Bs[nxt][kk_p][n_p + 1] = f2tf32(v1);
            As[nxt][a_k + 0][a_row_p] = f2tf32(pa.x);
            As[nxt][a_k + 1][a_row_p] = f2tf32(pa.y);
            As[nxt][a_k + 2][a_row_p] = f2tf32(pa.z);
            As[nxt][a_k + 3][a_row_p] = f2tf32(pa.w);
        }
        cur ^= 1;
    }

    // ---- epilogue: bias + float2 stores ----
    float* outb = out + (size_t)b * COUT_ * P_;
    #pragma unroll
    for (int am = 0; am < 2; am++) {
        int m0r = m_off + 16 * am + qq;     // rows m0r, m0r+8
        float bv0 = bias[m0r];
        float bv1 = bias[m0r + 8];
        #pragma unroll
        for (int bn = 0; bn < 2; bn++) {
            int col = n0 + n_off + 8 * bn + 2 * rr;
            float2 v0 = make_float2(acc[am][bn][0] + bv0, acc[am][bn][1] + bv0);
            float2 v1 = make_float2(acc[am][bn][2] + bv1, acc[am][bn][3] + bv1);
            *(float2*)&outb[(size_t)m0r * P_ + col]       = v0;
            *(float2*)&outb[(size_t)(m0r + 8) * P_ + col] = v1;
        }
    }
}

extern "C" void kernel_launch(void* const* d_in, const int* in_sizes, int n_in,
                              void* d_out, int out_size) {
    const float* rgb     = (const float*)d_in[0];
    const float* offsets = (const float*)d_in[1];
    const float* weight  = (const float*)d_in[2];
    const float* bias    = (const float*)d_in[3];
    float* out = (float*)d_out;

    dim3 grid(P_ / BN, 1, B_);   // 64 x 1 x 8 = 512 blocks
    fused_kernel<<<grid, NTHR>>>(rgb, offsets, weight, bias, out);
}

// round 5
// speedup vs baseline: 1.1839x; 1.1839x over previous
#include <cuda_runtime.h>
#include <math.h>
#include <stdint.h>

// Problem constants
#define B_     8
#define CIN_   64
#define COUT_  128
#define KH_    3
#define KW_    3
#define K_     9
#define H_     64
#define W_     64
#define P_     4096        // H*W
#define CK_    576         // CIN*K

// Scratch (static __device__ -> allocation-guard safe)
__device__ float    g_rgbt[B_ * P_ * CIN_];      // [b][p][c]  8.4 MB
__device__ uint32_t g_coltf[B_ * CK_ * P_];      // tf32 col, ck' = k*64+c, 75.5 MB
__device__ uint32_t g_wt[CK_ * COUT_];           // tf32 weight [ck'][m_perm] 294 KB

__device__ __forceinline__ uint32_t f2tf32(float f) {
    uint32_t u;
    asm("cvt.rna.tf32.f32 %0, %1;" : "=r"(u) : "f"(f));
    return u;
}

__device__ __forceinline__ int mperm(int m) {
    return (m & ~15) | (((m & 7) << 1) | ((m >> 3) & 1));
}

// ---------------------------------------------------------------------------
// Kernel 0a: transpose rgb [b][c][p] -> rgb_t [b][p][c]
// ---------------------------------------------------------------------------
__global__ __launch_bounds__(256)
void transpose_kernel(const float* __restrict__ rgb) {
    __shared__ float ts[64][65];
    const int b     = blockIdx.z;
    const int pbase = blockIdx.x * 64;
    const int tid   = threadIdx.x;

    // load: coalesced along p
    {
        int pp   = tid & 63;
        int crow = tid >> 6;          // 0..3
        const float* src = rgb + ((size_t)b * CIN_) * P_ + pbase + pp;
        #pragma unroll
        for (int r = 0; r < 16; r++) {
            int c = crow * 16 + r;
            ts[c][pp] = src[(size_t)c * P_];
        }
    }
    __syncthreads();
    // store: coalesced along c
    {
        int cc   = tid & 63;
        int prow = tid >> 6;
        float* dst = g_rgbt + ((size_t)b * P_ + pbase) * CIN_ + cc;
        #pragma unroll
        for (int r = 0; r < 16; r++) {
            int p = prow * 16 + r;
            dst[(size_t)p * CIN_] = ts[cc][p];
        }
    }
}

// ---------------------------------------------------------------------------
// Kernel 0b: weight [m][c*9+k] fp32 -> g_wt[ck'][m_perm] tf32, ck' = k*64+c
// ---------------------------------------------------------------------------
__global__ __launch_bounds__(256)
void wprep_kernel(const float* __restrict__ weight) {
    int idx = blockIdx.x * blockDim.x + threadIdx.x;
    if (idx >= CK_ * COUT_) return;
    int m   = idx & 127;
    int ckp = idx >> 7;
    int k   = ckp >> 6;
    int c   = ckp & 63;
    float v = weight[(size_t)m * CK_ + c * K_ + k];
    g_wt[(size_t)ckp * COUT_ + mperm(m)] = f2tf32(v);
}

// ---------------------------------------------------------------------------
// Kernel 1: deformable im2col v2.
// Thread per (b,k,p); channel quads via LDG.128 from rgb_t; writes tf32 col.
// ---------------------------------------------------------------------------
__global__ __launch_bounds__(256)
void im2col_kernel(const float* __restrict__ offsets) {
    int idx = blockIdx.x * blockDim.x + threadIdx.x;
    if (idx >= B_ * K_ * P_) return;

    int p  = idx & (P_ - 1);
    int bk = idx >> 12;
    int k  = bk % K_;
    int b  = bk / K_;

    int oy = p >> 6;
    int ox = p & 63;

    const float* offb = offsets + (size_t)b * 2 * K_ * P_;
    float dy = offb[(2 * k    ) * P_ + p];
    float dx = offb[(2 * k + 1) * P_ + p];

    float y = (float)(oy - 1 + k / KW_) + dy;
    float x = (float)(ox - 1 + k % KW_) + dx;

    float y0f = floorf(y);
    float x0f = floorf(x);
    float fy = y - y0f;
    float fx = x - x0f;
    int y0 = (int)y0f, x0 = (int)x0f;
    int y1 = y0 + 1,   x1 = x0 + 1;

    float w00 = (1.f - fy) * (1.f - fx);
    float w01 = (1.f - fy) * fx;
    float w10 = fy * (1.f - fx);
    float w11 = fy * fx;

    bool vy0 = (y0 >= 0) & (y0 < H_);
    bool vy1 = (y1 >= 0) & (y1 < H_);
    bool vx0 = (x0 >= 0) & (x0 < W_);
    bool vx1 = (x1 >= 0) & (x1 < W_);
    if (!(vy0 & vx0)) w00 = 0.f;
    if (!(vy0 & vx1)) w01 = 0.f;
    if (!(vy1 & vx0)) w10 = 0.f;
    if (!(vy1 & vx1)) w11 = 0.f;

    int cy0 = min(max(y0, 0), H_ - 1);
    int cy1 = min(max(y1, 0), H_ - 1);
    int cx0 = min(max(x0, 0), W_ - 1);
    int cx1 = min(max(x1, 0), W_ - 1);

    const float4* base = (const float4*)(g_rgbt + (size_t)b * P_ * CIN_);
    const float4* r00 = base + (size_t)(cy0 * W_ + cx0) * 16;
    const float4* r01 = base + (size_t)(cy0 * W_ + cx1) * 16;
    const float4* r10 = base + (size_t)(cy1 * W_ + cx0) * 16;
    const float4* r11 = base + (size_t)(cy1 * W_ + cx1) * 16;

    uint32_t* outp = g_coltf + ((size_t)(b * CK_ + k * 64)) * P_ + p;

    #pragma unroll 4
    for (int cq = 0; cq < 16; cq++) {
        float4 q00 = r00[cq];
        float4 q01 = r01[cq];
        float4 q10 = r10[cq];
        float4 q11 = r11[cq];
        float v0 = w00 * q00.x + w01 * q01.x + w10 * q10.x + w11 * q11.x;
        float v1 = w00 * q00.y + w01 * q01.y + w10 * q10.y + w11 * q11.y;
        float v2 = w00 * q00.z + w01 * q01.z + w10 * q10.z + w11 * q11.z;
        float v3 = w00 * q00.w + w01 * q01.w + w10 * q10.w + w11 * q11.w;
        outp[(size_t)(cq * 4 + 0) * P_] = f2tf32(v0);
        outp[(size_t)(cq * 4 + 1) * P_] = f2tf32(v1);
        outp[(size_t)(cq * 4 + 2) * P_] = f2tf32(v2);
        outp[(size_t)(cq * 4 + 3) * P_] = f2tf32(v3);
    }
}

// ---------------------------------------------------------------------------
// Kernel 2: TF32 tensor-core GEMM, pre-converted operands, uint4 producers.
// Block 128x128, BK=16, 256 threads, 8 warps (2m x 4n), warp tile 64x32.
// ---------------------------------------------------------------------------
#define BN 128
#define BKK 16
#define LDA 136   // 544B rows: 16B-aligned, conflict-free frag loads

__global__ __launch_bounds__(256)
void gemm_tf32_kernel(const float* __restrict__ bias,
                      float* __restrict__ out) {
    __shared__ uint32_t As[BKK][LDA];
    __shared__ uint32_t Bs[BKK][LDA];

    const int b   = blockIdx.z;
    const int n0  = blockIdx.x * BN;
    const int tid = threadIdx.x;
    const int lane = tid & 31;
    const int wid  = tid >> 5;
    const int m_off = (wid >> 2) * 64;
    const int n_off = (wid & 3) * 32;
    const int qq = lane >> 2;
    const int rr = lane & 3;

    const uint4* colb4 = (const uint4*)(g_coltf + (size_t)b * CK_ * P_);
    const uint4* wt4   = (const uint4*)g_wt;

    // producer mapping: row = tid>>4 (k), two 16B segs (t&15) and (t&15)+16
    const int prow = tid >> 4;       // 0..15
    const int pseg = tid & 15;       // 0..15

    float acc[4][4][4];
    #pragma unroll
    for (int i = 0; i < 4; i++)
        #pragma unroll
        for (int j = 0; j < 4; j++)
            #pragma unroll
            for (int c = 0; c < 4; c++) acc[i][j][c] = 0.f;

    // prefetch tile 0
    uint4 pa0 = wt4[(size_t)prow * 32 + pseg];
    uint4 pa1 = wt4[(size_t)prow * 32 + pseg + 16];
    uint4 pb0 = colb4[(size_t)prow * 1024 + (n0 >> 2) + pseg];
    uint4 pb1 = colb4[(size_t)prow * 1024 + (n0 >> 2) + pseg + 16];

    for (int k0 = 0; k0 < CK_; k0 += BKK) {
        *(uint4*)&As[prow][pseg * 4]      = pa0;
        *(uint4*)&As[prow][pseg * 4 + 64] = pa1;
        *(uint4*)&Bs[prow][pseg * 4]      = pb0;
        *(uint4*)&Bs[prow][pseg * 4 + 64] = pb1;
        __syncthreads();

        if (k0 + BKK < CK_) {
            int kr = k0 + BKK + prow;
            pa0 = wt4[(size_t)kr * 32 + pseg];
            pa1 = wt4[(size_t)kr * 32 + pseg + 16];
            pb0 = colb4[(size_t)kr * 1024 + (n0 >> 2) + pseg];
            pb1 = colb4[(size_t)kr * 1024 + (n0 >> 2) + pseg + 16];
        }

        #pragma unroll
        for (int ks = 0; ks < 2; ks++) {
            const int kk = ks * 8;
            uint32_t bf[4][2];
            #pragma unroll
            for (int bn = 0; bn < 4; bn++) {
                bf[bn][0] = Bs[kk + rr    ][n_off + 8 * bn + qq];
                bf[bn][1] = Bs[kk + rr + 4][n_off + 8 * bn + qq];
            }
            uint32_t af[4][4];
            #pragma unroll
            for (int am = 0; am < 4; am++) {
                uint2 v0 = *(const uint2*)&As[kk + rr    ][m_off + 16 * am + 2 * qq];
                uint2 v1 = *(const uint2*)&As[kk + rr + 4][m_off + 16 * am + 2 * qq];
                af[am][0] = v0.x; af[am][1] = v0.y;
                af[am][2] = v1.x; af[am][3] = v1.y;
            }
            #pragma unroll
            for (int am = 0; am < 4; am++)
                #pragma unroll
                for (int bn = 0; bn < 4; bn++) {
                    asm volatile(
                        "mma.sync.aligned.m16n8k8.row.col.f32.tf32.tf32.f32 "
                        "{%0,%1,%2,%3}, {%4,%5,%6,%7}, {%8,%9}, {%0,%1,%2,%3};"
                        : "+f"(acc[am][bn][0]), "+f"(acc[am][bn][1]),
                          "+f"(acc[am][bn][2]), "+f"(acc[am][bn][3])
                        : "r"(af[am][0]), "r"(af[am][1]),
                          "r"(af[am][2]), "r"(af[am][3]),
                          "r"(bf[bn][0]), "r"(bf[bn][1]));
                }
        }
        __syncthreads();
    }

    float* outb = out + (size_t)b * COUT_ * P_;
    #pragma unroll
    for (int am = 0; am < 4; am++) {
        int m0r = m_off + 16 * am + qq;
        float bv0 = bias[m0r];
        float bv1 = bias[m0r + 8];
        #pragma unroll
        for (int bn = 0; bn < 4; bn++) {
            int col = n0 + n_off + 8 * bn + 2 * rr;
            float2 v0 = make_float2(acc[am][bn][0] + bv0, acc[am][bn][1] + bv0);
            float2 v1 = make_float2(acc[am][bn][2] + bv1, acc[am][bn][3] + bv1);
            *(float2*)&outb[(size_t)m0r * P_ + col]       = v0;
            *(float2*)&outb[(size_t)(m0r + 8) * P_ + col] = v1;
        }
    }
}

extern "C" void kernel_launch(void* const* d_in, const int* in_sizes, int n_in,
                              void* d_out, int out_size) {
    const float* rgb     = (const float*)d_in[0];
    const float* offsets = (const float*)d_in[1];
    const float* weight  = (const float*)d_in[2];
    const float* bias    = (const float*)d_in[3];
    float* out = (float*)d_out;

    {
        dim3 grid(P_ / 64, 1, B_);            // 64 x 8 pixel-tiles
        transpose_kernel<<<grid, 256>>>(rgb);
    }
    {
        int total = CK_ * COUT_;
        wprep_kernel<<<(total + 255) / 256, 256>>>(weight);
    }
    {
        int total = B_ * K_ * P_;
        im2col_kernel<<<(total + 255) / 256, 256>>>(offsets);
    }
    {
        dim3 grid(P_ / BN, 1, B_);            // 32 x 1 x 8
        gemm_tf32_kernel<<<grid, 256>>>(bias, out);
    }
}

// round 6
// speedup vs baseline: 2.2566x; 1.9060x over previous
#include <cuda_runtime.h>
#include <cuda_fp16.h>
#include <math.h>
#include <stdint.h>

// Problem constants
#define B_     8
#define CIN_   64
#define COUT_  128
#define KH_    3
#define KW_    3
#define K_     9
#define H_     64
#define W_     64
#define P_     4096        // H*W
#define CK_    576         // CIN*K
#define KP_    288         // CK/2 k-pairs

// Scratch (static __device__ -> allocation-guard safe)
__device__ __half    g_colh[B_ * CK_ * P_];      // fp16 col, ck' = k*64+c  (37.7 MB)
__device__ uint32_t  g_wt[KP_ * COUT_];          // weight packed half2 (kpair, m_perm)

__device__ __forceinline__ int mperm(int m) {
    return (m & ~15) | (((m & 7) << 1) | ((m >> 3) & 1));
}

// ---------------------------------------------------------------------------
// Kernel 0: weight [m][c*9+k] fp32 -> g_wt[kp][m_perm] packed half2
//           half2 = (ck'=2kp, ck'=2kp+1), ck' = k*64+c
// ---------------------------------------------------------------------------
__global__ __launch_bounds__(256)
void wprep_kernel(const float* __restrict__ weight) {
    int idx = blockIdx.x * blockDim.x + threadIdx.x;
    if (idx >= KP_ * COUT_) return;
    int m  = idx & 127;
    int kp = idx >> 7;
    int ck0 = 2 * kp;
    int ck1 = 2 * kp + 1;
    int k0 = ck0 >> 6, c0 = ck0 & 63;
    int k1 = ck1 >> 6, c1 = ck1 & 63;
    __half h0 = __float2half(weight[(size_t)m * CK_ + c0 * K_ + k0]);
    __half h1 = __float2half(weight[(size_t)m * CK_ + c1 * K_ + k1]);
    uint32_t u = (uint32_t)__half_as_ushort(h0) |
                 ((uint32_t)__half_as_ushort(h1) << 16);
    g_wt[(size_t)kp * COUT_ + mperm(m)] = u;
}

// ---------------------------------------------------------------------------
// Kernel 1: deformable im2col, fp16 output, thread per (b, k, pixel-pair).
// Loads from rgb [c][p] (coalesced along p); stores half2 (2 pixels) per c.
// ---------------------------------------------------------------------------
__global__ __launch_bounds__(256)
void im2col_kernel(const float* __restrict__ rgb,
                   const float* __restrict__ offsets) {
    int idx = blockIdx.x * blockDim.x + threadIdx.x;
    if (idx >= B_ * K_ * (P_ / 2)) return;

    int p2 = idx & (P_ / 2 - 1);      // 0..2047
    int bk = idx >> 11;
    int k  = bk % K_;
    int b  = bk / K_;
    int p  = p2 * 2;

    int oy = p >> 6;
    int ox = p & 63;                  // even; ox+1 same row

    const float* offb = offsets + (size_t)b * 2 * K_ * P_;
    float dyA = offb[(2 * k    ) * P_ + p];
    float dyB = offb[(2 * k    ) * P_ + p + 1];
    float dxA = offb[(2 * k + 1) * P_ + p];
    float dxB = offb[(2 * k + 1) * P_ + p + 1];

    float ybase = (float)(oy - 1 + k / KW_);
    float xbase = (float)(ox - 1 + k % KW_);

    // pixel A
    float yA = ybase + dyA, xA = xbase + dxA;
    float y0fA = floorf(yA), x0fA = floorf(xA);
    float fyA = yA - y0fA, fxA = xA - x0fA;
    int y0A = (int)y0fA, x0A = (int)x0fA;
    float wA00 = (1.f - fyA) * (1.f - fxA);
    float wA01 = (1.f - fyA) * fxA;
    float wA10 = fyA * (1.f - fxA);
    float wA11 = fyA * fxA;
    {
        bool vy0 = (y0A >= 0) & (y0A < H_);
        bool vy1 = (y0A + 1 >= 0) & (y0A + 1 < H_);
        bool vx0 = (x0A >= 0) & (x0A < W_);
        bool vx1 = (x0A + 1 >= 0) & (x0A + 1 < W_);
        if (!(vy0 & vx0)) wA00 = 0.f;
        if (!(vy0 & vx1)) wA01 = 0.f;
        if (!(vy1 & vx0)) wA10 = 0.f;
        if (!(vy1 & vx1)) wA11 = 0.f;
    }
    int cyA0 = min(max(y0A, 0), H_ - 1);
    int cyA1 = min(max(y0A + 1, 0), H_ - 1);
    int cxA0 = min(max(x0A, 0), W_ - 1);
    int cxA1 = min(max(x0A + 1, 0), W_ - 1);
    int iA00 = cyA0 * W_ + cxA0, iA01 = cyA0 * W_ + cxA1;
    int iA10 = cyA1 * W_ + cxA0, iA11 = cyA1 * W_ + cxA1;

    // pixel B (= p+1)
    float yB = ybase + dyB, xB = xbase + 1.f + dxB;
    float y0fB = floorf(yB), x0fB = floorf(xB);
    float fyB = yB - y0fB, fxB = xB - x0fB;
    int y0B = (int)y0fB, x0B = (int)x0fB;
    float wB00 = (1.f - fyB) * (1.f - fxB);
    float wB01 = (1.f - fyB) * fxB;
    float wB10 = fyB * (1.f - fxB);
    float wB11 = fyB * fxB;
    {
        bool vy0 = (y0B >= 0) & (y0B < H_);
        bool vy1 = (y0B + 1 >= 0) & (y0B + 1 < H_);
        bool vx0 = (x0B >= 0) & (x0B < W_);
        bool vx1 = (x0B + 1 >= 0) & (x0B + 1 < W_);
        if (!(vy0 & vx0)) wB00 = 0.f;
        if (!(vy0 & vx1)) wB01 = 0.f;
        if (!(vy1 & vx0)) wB10 = 0.f;
        if (!(vy1 & vx1)) wB11 = 0.f;
    }
    int cyB0 = min(max(y0B, 0), H_ - 1);
    int cyB1 = min(max(y0B + 1, 0), H_ - 1);
    int cxB0 = min(max(x0B, 0), W_ - 1);
    int cxB1 = min(max(x0B + 1, 0), W_ - 1);
    int iB00 = cyB0 * W_ + cxB0, iB01 = cyB0 * W_ + cxB1;
    int iB10 = cyB1 * W_ + cxB0, iB11 = cyB1 * W_ + cxB1;

    const float* base = rgb + (size_t)b * CIN_ * P_;
    uint32_t* outp = (uint32_t*)g_colh
                   + ((((size_t)(b * CK_ + k * 64)) * P_ + p) >> 1);

    const float* pA00 = base + iA00;  const float* pA01 = base + iA01;
    const float* pA10 = base + iA10;  const float* pA11 = base + iA11;
    const float* pB00 = base + iB00;  const float* pB01 = base + iB01;
    const float* pB10 = base + iB10;  const float* pB11 = base + iB11;

    #pragma unroll 8
    for (int c = 0; c < CIN_; c++) {
        float va = wA00 * pA00[0] + wA01 * pA01[0]
                 + wA10 * pA10[0] + wA11 * pA11[0];
        float vb = wB00 * pB00[0] + wB01 * pB01[0]
                 + wB10 * pB10[0] + wB11 * pB11[0];
        __half2 h = __floats2half2_rn(va, vb);
        outp[(size_t)c * (P_ / 2)] = *(uint32_t*)&h;
        pA00 += P_; pA01 += P_; pA10 += P_; pA11 += P_;
        pB00 += P_; pB01 += P_; pB10 += P_; pB11 += P_;
    }
}

// ---------------------------------------------------------------------------
// Kernel 2: FP16 tensor-core GEMM (m16n8k16, fp32 accum).
// Block 128x128, BK=16 (8 kpair rows), 256 threads, 8 warps (2m x 4n).
// ---------------------------------------------------------------------------
#define BN 128
#define NKP 8      // kpair rows per tile
#define LDA 136

__global__ __launch_bounds__(256)
void gemm_fp16_kernel(const float* __restrict__ bias,
                      float* __restrict__ out) {
    __shared__ uint32_t As[NKP][LDA];   // packed half2 (k-pair) x m_perm
    __shared__ uint32_t Bs[NKP][LDA];   // packed half2 (k-pair) x n

    const int b   = blockIdx.z;
    const int n0  = blockIdx.x * BN;
    const int tid = threadIdx.x;
    const int lane = tid & 31;
    const int wid  = tid >> 5;
    const int m_off = (wid >> 2) * 64;
    const int n_off = (wid & 3) * 32;
    const int qq = lane >> 2;
    const int rr = lane & 3;

    const __half* colb = g_colh + (size_t)b * CK_ * P_;
    const uint4*  wt4  = (const uint4*)g_wt;

    // producer mapping: warp per kpair row, lane = 4-column segment
    const int prow = wid;            // 0..7
    const int pseg = lane;           // 0..31

    float acc[4][4][4];
    #pragma unroll
    for (int i = 0; i < 4; i++)
        #pragma unroll
        for (int j = 0; j < 4; j++)
            #pragma unroll
            for (int c = 0; c < 4; c++) acc[i][j][c] = 0.f;

    // prefetch tile 0
    uint4 pa;
    uint2 blo, bhi;
    {
        pa  = wt4[(size_t)prow * 32 + pseg];
        const __half* r0 = colb + (size_t)(2 * prow    ) * P_ + n0 + pseg * 4;
        const __half* r1 = colb + (size_t)(2 * prow + 1) * P_ + n0 + pseg * 4;
        blo = *(const uint2*)r0;
        bhi = *(const uint2*)r1;
    }

    for (int kp0 = 0; kp0 < KP_; kp0 += NKP) {
        *(uint4*)&As[prow][pseg * 4] = pa;
        uint32_t b0 = __byte_perm(blo.x, bhi.x, 0x5410);
        uint32_t b1 = __byte_perm(blo.x, bhi.x, 0x7632);
        uint32_t b2 = __byte_perm(blo.y, bhi.y, 0x5410);
        uint32_t b3 = __byte_perm(blo.y, bhi.y, 0x7632);
        *(uint4*)&Bs[prow][pseg * 4] = make_uint4(b0, b1, b2, b3);
        __syncthreads();

        if (kp0 + NKP < KP_) {
            int kr = kp0 + NKP + prow;
            pa = wt4[(size_t)kr * 32 + pseg];
            const __half* r0 = colb + (size_t)(2 * kr    ) * P_ + n0 + pseg * 4;
            const __half* r1 = colb + (size_t)(2 * kr + 1) * P_ + n0 + pseg * 4;
            blo = *(const uint2*)r0;
            bhi = *(const uint2*)r1;
        }

        // fragments + mma (one m16n8k16 per (am,bn))
        uint32_t bf[4][2];
        #pragma unroll
        for (int bn = 0; bn < 4; bn++) {
            bf[bn][0] = Bs[rr    ][n_off + 8 * bn + qq];
            bf[bn][1] = Bs[rr + 4][n_off + 8 * bn + qq];
        }
        uint32_t af[4][4];
        #pragma unroll
        for (int am = 0; am < 4; am++) {
            uint2 v0 = *(const uint2*)&As[rr    ][m_off + 16 * am + 2 * qq];
            uint2 v1 = *(const uint2*)&As[rr + 4][m_off + 16 * am + 2 * qq];
            af[am][0] = v0.x; af[am][1] = v0.y;
            af[am][2] = v1.x; af[am][3] = v1.y;
        }
        #pragma unroll
        for (int am = 0; am < 4; am++)
            #pragma unroll
            for (int bn = 0; bn < 4; bn++) {
                asm volatile(
                    "mma.sync.aligned.m16n8k16.row.col.f32.f16.f16.f32 "
                    "{%0,%1,%2,%3}, {%4,%5,%6,%7}, {%8,%9}, {%0,%1,%2,%3};"
                    : "+f"(acc[am][bn][0]), "+f"(acc[am][bn][1]),
                      "+f"(acc[am][bn][2]), "+f"(acc[am][bn][3])
                    : "r"(af[am][0]), "r"(af[am][1]),
                      "r"(af[am][2]), "r"(af[am][3]),
                      "r"(bf[bn][0]), "r"(bf[bn][1]));
            }
        __syncthreads();
    }

    float* outb = out + (size_t)b * COUT_ * P_;
    #pragma unroll
    for (int am = 0; am < 4; am++) {
        int m0r = m_off + 16 * am + qq;
        float bv0 = bias[m0r];
        float bv1 = bias[m0r + 8];
        #pragma unroll
        for (int bn = 0; bn < 4; bn++) {
            int col = n0 + n_off + 8 * bn + 2 * rr;
            float2 v0 = make_float2(acc[am][bn][0] + bv0, acc[am][bn][1] + bv0);
            float2 v1 = make_float2(acc[am][bn][2] + bv1, acc[am][bn][3] + bv1);
            *(float2*)&outb[(size_t)m0r * P_ + col]       = v0;
            *(float2*)&outb[(size_t)(m0r + 8) * P_ + col] = v1;
        }
    }
}

extern "C" void kernel_launch(void* const* d_in, const int* in_sizes, int n_in,
                              void* d_out, int out_size) {
    const float* rgb     = (const float*)d_in[0];
    const float* offsets = (const float*)d_in[1];
    const float* weight  = (const float*)d_in[2];
    const float* bias    = (const float*)d_in[3];
    float* out = (float*)d_out;

    {
        int total = KP_ * COUT_;
        wprep_kernel<<<(total + 255) / 256, 256>>>(weight);
    }
    {
        int total = B_ * K_ * (P_ / 2);       // 147456
        im2col_kernel<<<(total + 255) / 256, 256>>>(rgb, offsets);
    }
    {
        dim3 grid(P_ / BN, 1, B_);            // 32 x 1 x 8
        gemm_fp16_kernel<<<grid, 256>>>(bias, out);
    }
}